// round 2
// baseline (speedup 1.0000x reference)
#include <cuda_runtime.h>

// Per-frame precomputed matrices: M[f] = initial_extrinsics[f] @ inv(c2w[f])
// 10000 frames x 4 float4 rows = 640 KB, static device scratch (no allocs).
#define NF_MAX 10000
__device__ float4 g_M[NF_MAX * 4];

// ---------------------------------------------------------------------------
// Phase 1: per-frame precompute (tiny: 10,000 threads). Done in double for
// numerical headroom; cost is negligible relative to the 128 MB output write.
// ---------------------------------------------------------------------------
__global__ void precompute_kernel(const float* __restrict__ r,
                                  const float* __restrict__ t,
                                  const float* __restrict__ E,
                                  int nf) {
    int f = blockIdx.x * blockDim.x + threadIdx.x;
    if (f >= nf) return;

    double v0 = (double)r[3 * f + 0];
    double v1 = (double)r[3 * f + 1];
    double v2 = (double)r[3 * f + 2];

    double n = sqrt(v0 * v0 + v1 * v1 + v2 * v2) + 1e-15;
    double a = sin(n) / n;
    double b = (1.0 - cos(n)) / (n * n);

    // Reference vec2skew: columns are s0,s1,s2 -> TRANSPOSE of standard skew:
    //   S = [[ 0,  v2, -v1],
    //        [-v2,  0,  v0],
    //        [ v1, -v0,  0]]
    double S[3][3] = {{0.0,  v2, -v1},
                      {-v2, 0.0,  v0},
                      { v1, -v0, 0.0}};

    double S2[3][3];
#pragma unroll
    for (int i = 0; i < 3; i++)
#pragma unroll
        for (int j = 0; j < 3; j++)
            S2[i][j] = S[i][0] * S[0][j] + S[i][1] * S[1][j] + S[i][2] * S[2][j];

    double R[3][3];
#pragma unroll
    for (int i = 0; i < 3; i++)
#pragma unroll
        for (int j = 0; j < 3; j++)
            R[i][j] = (i == j ? 1.0 : 0.0) + a * S[i][j] + b * S2[i][j];

    // c2w = [[R, t],[0,0,0,1]] is exactly rigid -> inv = [[R^T, -R^T t],[0,0,0,1]]
    double tv0 = (double)t[3 * f + 0];
    double tv1 = (double)t[3 * f + 1];
    double tv2 = (double)t[3 * f + 2];

    double Inv[3][4];  // rows 0..2 of inverse; row 3 is (0,0,0,1)
#pragma unroll
    for (int i = 0; i < 3; i++) {
        Inv[i][0] = R[0][i];  // R^T
        Inv[i][1] = R[1][i];
        Inv[i][2] = R[2][i];
        Inv[i][3] = -(R[0][i] * tv0 + R[1][i] * tv1 + R[2][i] * tv2);
    }

    // M = E0 @ Inv  (full 4x4 multiply; Inv row 3 = e3)
    const float* E0 = E + 16 * f;
#pragma unroll
    for (int i = 0; i < 4; i++) {
        double e0 = (double)E0[i * 4 + 0];
        double e1 = (double)E0[i * 4 + 1];
        double e2 = (double)E0[i * 4 + 2];
        double e3 = (double)E0[i * 4 + 3];
        float4 row;
        row.x = (float)(e0 * Inv[0][0] + e1 * Inv[1][0] + e2 * Inv[2][0]);
        row.y = (float)(e0 * Inv[0][1] + e1 * Inv[1][1] + e2 * Inv[2][1]);
        row.z = (float)(e0 * Inv[0][2] + e1 * Inv[1][2] + e2 * Inv[2][2]);
        row.w = (float)(e0 * Inv[0][3] + e1 * Inv[1][3] + e2 * Inv[2][3] + e3);
        g_M[f * 4 + i] = row;
    }
}

// ---------------------------------------------------------------------------
// Phase 2: gather. One thread per float4 chunk (4 threads per ray).
// Warp writes 512 B contiguous; cam_id load is 4-way same-address (broadcast);
// table reads hit L2 (640 KB resident). cam_id is INT32 (JAX x64 disabled).
// ---------------------------------------------------------------------------
__global__ void gather_kernel(const int* __restrict__ cam,
                              float4* __restrict__ out,
                              int n_chunks, int nf) {
    int c = blockIdx.x * blockDim.x + threadIdx.x;
    if (c >= n_chunks) return;
    int ray = c >> 2;
    int q   = c & 3;
    int f = cam[ray];
    // clamp defensively (1 ALU op; kernel is memory-bound)
    f = min(max(f, 0), nf - 1);
    out[c] = __ldg(&g_M[f * 4 + q]);
}

extern "C" void kernel_launch(void* const* d_in, const int* in_sizes, int n_in,
                              void* d_out, int out_size) {
    const float* r   = (const float*)d_in[0];   // (NF, 3)
    const float* t   = (const float*)d_in[1];   // (NF, 3)
    const float* E   = (const float*)d_in[2];   // (NF, 4, 4)
    const int*   cam = (const int*)d_in[3];     // (NR,) int32 (JAX default x64 off)

    int nf = in_sizes[0] / 3;
    if (nf > NF_MAX) nf = NF_MAX;
    int nr = in_sizes[3];

    precompute_kernel<<<(nf + 127) / 128, 128>>>(r, t, E, nf);

    int n_chunks = nr * 4;  // one float4 per thread
    gather_kernel<<<(n_chunks + 255) / 256, 256>>>(cam, (float4*)d_out, n_chunks, nf);
}

// round 3
// speedup vs baseline: 1.0825x; 1.0825x over previous
#include <cuda_runtime.h>

// Per-frame precomputed matrices: M[f] = initial_extrinsics[f] @ inv(c2w[f])
// 10000 frames x 4 float4 rows = 640 KB static device scratch.
#define NF_MAX 10000
__device__ float4 g_M[NF_MAX * 4];

// ---------------------------------------------------------------------------
// Phase 1: per-frame precompute, all fp32 (fp64 trig was ~13us; fp32 error
// on (1-cos n)/n^2 at n~0.09 is ~2.5e-5 rel, far under the 1e-3 gate).
// ---------------------------------------------------------------------------
__global__ void precompute_kernel(const float* __restrict__ r,
                                  const float* __restrict__ t,
                                  const float* __restrict__ E,
                                  int nf) {
    int f = blockIdx.x * blockDim.x + threadIdx.x;
    if (f >= nf) return;

    float v0 = r[3 * f + 0];
    float v1 = r[3 * f + 1];
    float v2 = r[3 * f + 2];

    float n = sqrtf(v0 * v0 + v1 * v1 + v2 * v2) + 1e-15f;
    float sn, cn;
    __sincosf(n, &sn, &cn);          // n < ~0.3: fast path plenty accurate
    float a = sn / n;
    float b = (1.0f - cn) / (n * n);

    // Reference vec2skew (columns are s0,s1,s2 -> transpose of standard skew):
    //   S = [[ 0,  v2, -v1],
    //        [-v2,  0,  v0],
    //        [ v1, -v0,  0]]
    float S[3][3] = {{0.0f,  v2, -v1},
                     {-v2, 0.0f,  v0},
                     { v1, -v0, 0.0f}};

    float S2[3][3];
#pragma unroll
    for (int i = 0; i < 3; i++)
#pragma unroll
        for (int j = 0; j < 3; j++)
            S2[i][j] = S[i][0] * S[0][j] + S[i][1] * S[1][j] + S[i][2] * S[2][j];

    float R[3][3];
#pragma unroll
    for (int i = 0; i < 3; i++)
#pragma unroll
        for (int j = 0; j < 3; j++)
            R[i][j] = (i == j ? 1.0f : 0.0f) + a * S[i][j] + b * S2[i][j];

    // c2w = [[R, t],[0,0,0,1]] rigid -> inv = [[R^T, -R^T t],[0,0,0,1]]
    float tv0 = t[3 * f + 0];
    float tv1 = t[3 * f + 1];
    float tv2 = t[3 * f + 2];

    float Inv[3][4];
#pragma unroll
    for (int i = 0; i < 3; i++) {
        Inv[i][0] = R[0][i];
        Inv[i][1] = R[1][i];
        Inv[i][2] = R[2][i];
        Inv[i][3] = -(R[0][i] * tv0 + R[1][i] * tv1 + R[2][i] * tv2);
    }

    // M = E0 @ Inv  (Inv row 3 = e3)
    const float4* E0 = (const float4*)(E + 16 * f);
#pragma unroll
    for (int i = 0; i < 4; i++) {
        float4 e = E0[i];
        float4 row;
        row.x = e.x * Inv[0][0] + e.y * Inv[1][0] + e.z * Inv[2][0];
        row.y = e.x * Inv[0][1] + e.y * Inv[1][1] + e.z * Inv[2][1];
        row.z = e.x * Inv[0][2] + e.y * Inv[1][2] + e.z * Inv[2][2];
        row.w = e.x * Inv[0][3] + e.y * Inv[1][3] + e.z * Inv[2][3] + e.w;
        g_M[f * 4 + i] = row;
    }
}

// ---------------------------------------------------------------------------
// Phase 2: gather. One thread per HALF-ray (2 float4 chunks) -> MLP=2 per
// thread, half the cam loads. Warp stores 1 KB contiguous. Streaming stores
// (__stcs): output is never re-read, keep table lines in L2.
// ---------------------------------------------------------------------------
__global__ void gather_kernel(const int* __restrict__ cam,
                              float4* __restrict__ out,
                              int n_half, int nf) {
    int i = blockIdx.x * blockDim.x + threadIdx.x;
    if (i >= n_half) return;
    int ray = i >> 1;
    int h   = (i & 1) << 1;          // 0 or 2 (which pair of rows)
    int f = cam[ray];
    f = min(max(f, 0), nf - 1);      // defensive clamp, 1 ALU op
    const float4* src = &g_M[f * 4 + h];
    float4 r0 = __ldg(src);
    float4 r1 = __ldg(src + 1);
    __stcs(&out[2 * i],     r0);
    __stcs(&out[2 * i + 1], r1);
}

extern "C" void kernel_launch(void* const* d_in, const int* in_sizes, int n_in,
                              void* d_out, int out_size) {
    const float* r   = (const float*)d_in[0];   // (NF, 3)
    const float* t   = (const float*)d_in[1];   // (NF, 3)
    const float* E   = (const float*)d_in[2];   // (NF, 4, 4)
    const int*   cam = (const int*)d_in[3];     // (NR,) int32

    int nf = in_sizes[0] / 3;
    if (nf > NF_MAX) nf = NF_MAX;
    int nr = in_sizes[3];

    precompute_kernel<<<(nf + 127) / 128, 128>>>(r, t, E, nf);

    int n_half = nr * 2;             // two float4 chunks per thread
    gather_kernel<<<(n_half + 255) / 256, 256>>>(cam, (float4*)d_out, n_half, nf);
}

// round 4
// speedup vs baseline: 1.3209x; 1.2203x over previous
#include <cuda_runtime.h>

// Per-frame precomputed matrices: M[f] = initial_extrinsics[f] @ inv(c2w[f])
// 10000 frames x 4 float4 rows = 640 KB static device scratch.
#define NF_MAX 10000
__device__ float4 g_M[NF_MAX * 4];

// ---------------------------------------------------------------------------
// Phase 1: per-frame precompute, all fp32 (~2us).
// ---------------------------------------------------------------------------
__global__ void precompute_kernel(const float* __restrict__ r,
                                  const float* __restrict__ t,
                                  const float* __restrict__ E,
                                  int nf) {
    int f = blockIdx.x * blockDim.x + threadIdx.x;
    if (f >= nf) return;

    float v0 = r[3 * f + 0];
    float v1 = r[3 * f + 1];
    float v2 = r[3 * f + 2];

    float n = sqrtf(v0 * v0 + v1 * v1 + v2 * v2) + 1e-15f;
    float sn, cn;
    __sincosf(n, &sn, &cn);
    float a = sn / n;
    float b = (1.0f - cn) / (n * n);

    // Reference vec2skew (transpose of standard skew):
    float S[3][3] = {{0.0f,  v2, -v1},
                     {-v2, 0.0f,  v0},
                     { v1, -v0, 0.0f}};

    float S2[3][3];
#pragma unroll
    for (int i = 0; i < 3; i++)
#pragma unroll
        for (int j = 0; j < 3; j++)
            S2[i][j] = S[i][0] * S[0][j] + S[i][1] * S[1][j] + S[i][2] * S[2][j];

    float R[3][3];
#pragma unroll
    for (int i = 0; i < 3; i++)
#pragma unroll
        for (int j = 0; j < 3; j++)
            R[i][j] = (i == j ? 1.0f : 0.0f) + a * S[i][j] + b * S2[i][j];

    // rigid inverse of c2w
    float tv0 = t[3 * f + 0];
    float tv1 = t[3 * f + 1];
    float tv2 = t[3 * f + 2];

    float Inv[3][4];
#pragma unroll
    for (int i = 0; i < 3; i++) {
        Inv[i][0] = R[0][i];
        Inv[i][1] = R[1][i];
        Inv[i][2] = R[2][i];
        Inv[i][3] = -(R[0][i] * tv0 + R[1][i] * tv1 + R[2][i] * tv2);
    }

    const float4* E0 = (const float4*)(E + 16 * f);
#pragma unroll
    for (int i = 0; i < 4; i++) {
        float4 e = E0[i];
        float4 row;
        row.x = e.x * Inv[0][0] + e.y * Inv[1][0] + e.z * Inv[2][0];
        row.y = e.x * Inv[0][1] + e.y * Inv[1][1] + e.z * Inv[2][1];
        row.z = e.x * Inv[0][2] + e.y * Inv[1][2] + e.z * Inv[2][2];
        row.w = e.x * Inv[0][3] + e.y * Inv[1][3] + e.z * Inv[2][3] + e.w;
        g_M[f * 4 + i] = row;
    }
}

// ---------------------------------------------------------------------------
// Phase 2: gather. R2 mapping (one float4 chunk per (thread,iter): the 4
// lanes of a ray fetch its 64B entry in ONE LDG.128 -> ~1 L1 wavefront/ray),
// plus ILP=4: 4 independent cam->table chains per thread to hide L2 latency.
// ---------------------------------------------------------------------------
#define GATHER_ILP 4
__global__ void gather_kernel(const int* __restrict__ cam,
                              float4* __restrict__ out,
                              int n_chunks, int nf) {
    int base = blockIdx.x * (blockDim.x * GATHER_ILP) + threadIdx.x;

    float4 v[GATHER_ILP];
#pragma unroll
    for (int k = 0; k < GATHER_ILP; k++) {
        int c = base + k * blockDim.x;
        if (c < n_chunks) {
            int ray = c >> 2;
            int q   = c & 3;
            int f = cam[ray];
            f = min(max(f, 0), nf - 1);
            v[k] = __ldg(&g_M[f * 4 + q]);
        }
    }
#pragma unroll
    for (int k = 0; k < GATHER_ILP; k++) {
        int c = base + k * blockDim.x;
        if (c < n_chunks) out[c] = v[k];
    }
}

extern "C" void kernel_launch(void* const* d_in, const int* in_sizes, int n_in,
                              void* d_out, int out_size) {
    const float* r   = (const float*)d_in[0];   // (NF, 3)
    const float* t   = (const float*)d_in[1];   // (NF, 3)
    const float* E   = (const float*)d_in[2];   // (NF, 4, 4)
    const int*   cam = (const int*)d_in[3];     // (NR,) int32

    int nf = in_sizes[0] / 3;
    if (nf > NF_MAX) nf = NF_MAX;
    int nr = in_sizes[3];

    precompute_kernel<<<(nf + 127) / 128, 128>>>(r, t, E, nf);

    int n_chunks = nr * 4;
    int threads = 256;
    int per_block = threads * GATHER_ILP;
    int grid = (n_chunks + per_block - 1) / per_block;
    gather_kernel<<<grid, threads>>>(cam, (float4*)d_out, n_chunks, nf);
}

// round 5
// speedup vs baseline: 1.5146x; 1.1466x over previous
#include <cuda_runtime.h>

// Per-frame precomputed matrices: M[f] = initial_extrinsics[f] @ inv(c2w[f])
// 10000 frames x 4 float4 rows = 640 KB static device scratch.
#define NF_MAX 10000
__device__ float4 g_M[NF_MAX * 4];

// ---------------------------------------------------------------------------
// Phase 1: per-frame precompute, all fp32 (~2us).
// ---------------------------------------------------------------------------
__global__ void precompute_kernel(const float* __restrict__ r,
                                  const float* __restrict__ t,
                                  const float* __restrict__ E,
                                  int nf) {
    int f = blockIdx.x * blockDim.x + threadIdx.x;
    if (f >= nf) return;

    float v0 = r[3 * f + 0];
    float v1 = r[3 * f + 1];
    float v2 = r[3 * f + 2];

    float n = sqrtf(v0 * v0 + v1 * v1 + v2 * v2) + 1e-15f;
    float sn, cn;
    __sincosf(n, &sn, &cn);
    float a = sn / n;
    float b = (1.0f - cn) / (n * n);

    // Reference vec2skew (transpose of standard skew):
    float S[3][3] = {{0.0f,  v2, -v1},
                     {-v2, 0.0f,  v0},
                     { v1, -v0, 0.0f}};

    float S2[3][3];
#pragma unroll
    for (int i = 0; i < 3; i++)
#pragma unroll
        for (int j = 0; j < 3; j++)
            S2[i][j] = S[i][0] * S[0][j] + S[i][1] * S[1][j] + S[i][2] * S[2][j];

    float R[3][3];
#pragma unroll
    for (int i = 0; i < 3; i++)
#pragma unroll
        for (int j = 0; j < 3; j++)
            R[i][j] = (i == j ? 1.0f : 0.0f) + a * S[i][j] + b * S2[i][j];

    // rigid inverse of c2w
    float tv0 = t[3 * f + 0];
    float tv1 = t[3 * f + 1];
    float tv2 = t[3 * f + 2];

    float Inv[3][4];
#pragma unroll
    for (int i = 0; i < 3; i++) {
        Inv[i][0] = R[0][i];
        Inv[i][1] = R[1][i];
        Inv[i][2] = R[2][i];
        Inv[i][3] = -(R[0][i] * tv0 + R[1][i] * tv1 + R[2][i] * tv2);
    }

    const float4* E0 = (const float4*)(E + 16 * f);
#pragma unroll
    for (int i = 0; i < 4; i++) {
        float4 e = E0[i];
        float4 row;
        row.x = e.x * Inv[0][0] + e.y * Inv[1][0] + e.z * Inv[2][0];
        row.y = e.x * Inv[0][1] + e.y * Inv[1][1] + e.z * Inv[2][1];
        row.z = e.x * Inv[0][2] + e.y * Inv[1][2] + e.z * Inv[2][2];
        row.w = e.x * Inv[0][3] + e.y * Inv[1][3] + e.z * Inv[2][3] + e.w;
        g_M[f * 4 + i] = row;
    }
}

// ---------------------------------------------------------------------------
// Phase 2: gather. Quad-lane layout (4 lanes of a ray fetch its 64B entry in
// one warp LDG -> ~1 L1 wavefront/ray) + ILP=8 for deep MLP. Full blocks run
// guard-free so ptxas front-batches all 8 load chains.
// ---------------------------------------------------------------------------
#define GATHER_ILP 8
__global__ void __launch_bounds__(256) gather_kernel(
        const int* __restrict__ cam,
        float4* __restrict__ out,
        int n_chunks, int nf) {
    int base = blockIdx.x * (blockDim.x * GATHER_ILP) + threadIdx.x;

    if (base + (GATHER_ILP - 1) * blockDim.x < n_chunks) {
        // fast path: no per-iteration guards
        float4 v[GATHER_ILP];
#pragma unroll
        for (int k = 0; k < GATHER_ILP; k++) {
            int c = base + k * blockDim.x;
            int ray = c >> 2;
            int q   = c & 3;
            int f = cam[ray];
            f = min(max(f, 0), nf - 1);
            v[k] = __ldg(&g_M[f * 4 + q]);
        }
#pragma unroll
        for (int k = 0; k < GATHER_ILP; k++)
            out[base + k * blockDim.x] = v[k];
    } else {
        // tail block
#pragma unroll
        for (int k = 0; k < GATHER_ILP; k++) {
            int c = base + k * blockDim.x;
            if (c < n_chunks) {
                int ray = c >> 2;
                int q   = c & 3;
                int f = cam[ray];
                f = min(max(f, 0), nf - 1);
                out[c] = __ldg(&g_M[f * 4 + q]);
            }
        }
    }
}

extern "C" void kernel_launch(void* const* d_in, const int* in_sizes, int n_in,
                              void* d_out, int out_size) {
    const float* r   = (const float*)d_in[0];   // (NF, 3)
    const float* t   = (const float*)d_in[1];   // (NF, 3)
    const float* E   = (const float*)d_in[2];   // (NF, 4, 4)
    const int*   cam = (const int*)d_in[3];     // (NR,) int32

    int nf = in_sizes[0] / 3;
    if (nf > NF_MAX) nf = NF_MAX;
    int nr = in_sizes[3];

    precompute_kernel<<<(nf + 127) / 128, 128>>>(r, t, E, nf);

    int n_chunks = nr * 4;
    int threads = 256;
    int per_block = threads * GATHER_ILP;
    int grid = (n_chunks + per_block - 1) / per_block;
    gather_kernel<<<grid, threads>>>(cam, (float4*)d_out, n_chunks, nf);
}